// round 1
// baseline (speedup 1.0000x reference)
#include <cuda_runtime.h>
#include <math.h>

// Problem constants (B, C, H, W) = (2048, 1, 128, 128)
#define NB      2048
#define HW      128
#define IMG_PIX 16384      // 128*128
#define CROP_PIX 4096      // 64*64

// Output layout: concatenation of (target, target_cut, target_scene, target_raw)
#define OFF_TARGET 0
#define OFF_CUT    (2048u * 4096u)                    // 8,388,608
#define OFF_SCENE  (2u * 2048u * 4096u)               // 16,777,216
#define OFF_RAW    (OFF_SCENE + 2048u * 16384u)       // 50,331,648

__global__ __launch_bounds__(256)
void kd_fused_kernel(const float* __restrict__ image,
                     const float* __restrict__ azimuth,
                     const float* __restrict__ alpha,
                     float* __restrict__ out)
{
    const int b = blockIdx.x;

    const float* img   = image + (size_t)b * IMG_PIX;
    float* targ  = out + OFF_TARGET + (size_t)b * CROP_PIX;
    float* cut   = out + OFF_CUT    + (size_t)b * CROP_PIX;
    float* scene = out + OFF_SCENE  + (size_t)b * IMG_PIX;
    float* raw   = out + OFF_RAW    + (size_t)b * IMG_PIX;

    // Box bounds, replicating reference float32 arithmetic:
    // x_up = round(CX + alpha[0]*70/2), etc. round = half-to-even (jnp.round).
    float a0 = alpha[0], a1 = alpha[1], a2 = alpha[2], a3 = alpha[3];
    float xu = nearbyintf(__fadd_rn(64.0f, __fmul_rn(__fmul_rn(a0, 70.0f), 0.5f)));
    float xd = nearbyintf(__fsub_rn(64.0f, __fmul_rn(__fmul_rn(a1, 70.0f), 0.5f)));
    float yu = nearbyintf(__fadd_rn(64.0f, __fmul_rn(__fmul_rn(a2, 70.0f), 0.5f)));
    float yd = nearbyintf(__fsub_rn(64.0f, __fmul_rn(__fmul_rn(a3, 70.0f), 0.5f)));

    // Rotation angle: masks[b] = rotate(box, -azimuth[b]); a = deg2rad(-az)
    const float ang = __fmul_rn(-azimuth[b], 0.017453292519943295f);
    float sn, cs;
    sincosf(ang, &sn, &cs);
    const float nsn = -sn;

    // 4096 float4 per image, 256 threads -> 16 iterations
    for (int i = threadIdx.x; i < IMG_PIX / 4; i += 256) {
        const int r  = i >> 5;         // row 0..127
        const int c0 = (i & 31) << 2;  // col 0,4,...,124

        const float4 v = reinterpret_cast<const float4*>(img)[i];

        const float Y  = (float)r - 63.5f;
        const float ty = __fmul_rn(sn, Y);   // sin*Y  (xin term)
        const float cy = __fmul_rn(cs, Y);   // cos*Y  (yin term)

        float tg[4], sc[4];
        const float vv[4] = {v.x, v.y, v.z, v.w};

        #pragma unroll
        for (int k = 0; k < 4; k++) {
            const float X   = (float)(c0 + k) - 63.5f;
            // xin = cos*X + sin*Y ; yin = (-sin)*X + cos*Y   (no FMA, match ref)
            const float xin = __fadd_rn(__fmul_rn(cs,  X), ty);
            const float yin = __fadd_rn(__fmul_rn(nsn, X), cy);
            // col = floor((xin + 63.5) + 0.5); floor() elided via integer-bound trick
            const float tcol = __fadd_rn(__fadd_rn(xin, 63.5f), 0.5f);
            const float trow = __fadd_rn(__fadd_rn(yin, 63.5f), 0.5f);
            // box: rows use x-bounds, cols use y-bounds (per reference)
            const bool m = (trow >= xd) & (trow < xu) & (tcol >= yd) & (tcol < yu);
            tg[k] = m ? vv[k] : 0.0f;   // image * mask
            sc[k] = m ? 0.0f  : vv[k];  // image * (mask == 0)
        }

        // target_raw: straight copy
        reinterpret_cast<float4*>(raw)[i] = v;
        // target_scene
        reinterpret_cast<float4*>(scene)[i] = make_float4(sc[0], sc[1], sc[2], sc[3]);

        // Central 64x64 crop [32:96]x[32:96] -> target, target_cut
        if (r >= 32 && r < 96 && c0 >= 32 && c0 < 96) {
            const int ci4 = (((r - 32) << 6) + (c0 - 32)) >> 2;
            reinterpret_cast<float4*>(targ)[ci4] = make_float4(tg[0], tg[1], tg[2], tg[3]);
            float4 cu;
            cu.x = fminf(__fmul_rn(v.x, 2.0f), 1.0f);
            cu.y = fminf(__fmul_rn(v.y, 2.0f), 1.0f);
            cu.z = fminf(__fmul_rn(v.z, 2.0f), 1.0f);
            cu.w = fminf(__fmul_rn(v.w, 2.0f), 1.0f);
            reinterpret_cast<float4*>(cut)[ci4] = cu;
        }
    }
}

extern "C" void kernel_launch(void* const* d_in, const int* in_sizes, int n_in,
                              void* d_out, int out_size)
{
    const float* image   = (const float*)d_in[0];
    const float* azimuth = (const float*)d_in[1];
    const float* alpha   = (const float*)d_in[2];
    float* out = (float*)d_out;

    kd_fused_kernel<<<NB, 256>>>(image, azimuth, alpha, out);
}

// round 3
// speedup vs baseline: 1.0454x; 1.0454x over previous
#include <cuda_runtime.h>
#include <math.h>

// Problem constants (B, C, H, W) = (2048, 1, 128, 128)
#define NB       2048
#define IMG_PIX  16384     // 128*128
#define CROP_PIX 4096      // 64*64

// Output layout: concatenation of (target, target_cut, target_scene, target_raw)
#define OFF_TARGET 0
#define OFF_CUT    (2048u * 4096u)
#define OFF_SCENE  (2u * 2048u * 4096u)
#define OFF_RAW    (OFF_SCENE + 2048u * 16384u)

// Process one float4 (index i within the image): compute mask, emit all stores.
__device__ __forceinline__ void process4(
    int i, float4 v,
    float sn, float cs, float nsn,
    float xd, float xu, float yd, float yu,
    float* __restrict__ targ, float* __restrict__ cut,
    float* __restrict__ scene, float* __restrict__ raw)
{
    const int r  = i >> 5;         // row 0..127
    const int c0 = (i & 31) << 2;  // col 0,4,...,124

    const float Y  = (float)r - 63.5f;
    const float ty = __fmul_rn(sn, Y);   // sin*Y  (xin term)
    const float cy = __fmul_rn(cs, Y);   // cos*Y  (yin term)

    float tg[4], sc[4];
    const float vv[4] = {v.x, v.y, v.z, v.w};

    #pragma unroll
    for (int k = 0; k < 4; k++) {
        const float X   = (float)(c0 + k) - 63.5f;
        // xin = cos*X + sin*Y ; yin = (-sin)*X + cos*Y  (no FMA, match reference)
        const float xin = __fadd_rn(__fmul_rn(cs,  X), ty);
        const float yin = __fadd_rn(__fmul_rn(nsn, X), cy);
        const float tcol = __fadd_rn(__fadd_rn(xin, 63.5f), 0.5f);
        const float trow = __fadd_rn(__fadd_rn(yin, 63.5f), 0.5f);
        const bool m = (trow >= xd) & (trow < xu) & (tcol >= yd) & (tcol < yu);
        tg[k] = m ? vv[k] : 0.0f;   // image * mask
        sc[k] = m ? 0.0f  : vv[k];  // image * (mask == 0)
    }

    // Streaming stores: outputs are never re-read by this kernel.
    __stcs(reinterpret_cast<float4*>(raw) + i, v);
    __stcs(reinterpret_cast<float4*>(scene) + i,
           make_float4(sc[0], sc[1], sc[2], sc[3]));

    // Central 64x64 crop [32:96]x[32:96] -> target, target_cut
    if (r >= 32 && r < 96 && c0 >= 32 && c0 < 96) {
        const int ci4 = (((r - 32) << 6) + (c0 - 32)) >> 2;
        __stcs(reinterpret_cast<float4*>(targ) + ci4,
               make_float4(tg[0], tg[1], tg[2], tg[3]));
        float4 cu;
        cu.x = fminf(__fmul_rn(v.x, 2.0f), 1.0f);
        cu.y = fminf(__fmul_rn(v.y, 2.0f), 1.0f);
        cu.z = fminf(__fmul_rn(v.z, 2.0f), 1.0f);
        cu.w = fminf(__fmul_rn(v.w, 2.0f), 1.0f);
        __stcs(reinterpret_cast<float4*>(cut) + ci4, cu);
    }
}

__global__ __launch_bounds__(256)
void kd_fused_kernel(const float* __restrict__ image,
                     const float* __restrict__ azimuth,
                     const float* __restrict__ alpha,
                     float* __restrict__ out)
{
    const int b = blockIdx.x;

    const float* img   = image + (size_t)b * IMG_PIX;
    float* targ  = out + OFF_TARGET + (size_t)b * CROP_PIX;
    float* cut   = out + OFF_CUT    + (size_t)b * CROP_PIX;
    float* scene = out + OFF_SCENE  + (size_t)b * IMG_PIX;
    float* raw   = out + OFF_RAW    + (size_t)b * IMG_PIX;

    // Box bounds, replicating reference float32 arithmetic (round = half-to-even).
    float a0 = alpha[0], a1 = alpha[1], a2 = alpha[2], a3 = alpha[3];
    float xu = nearbyintf(__fadd_rn(64.0f, __fmul_rn(__fmul_rn(a0, 70.0f), 0.5f)));
    float xd = nearbyintf(__fsub_rn(64.0f, __fmul_rn(__fmul_rn(a1, 70.0f), 0.5f)));
    float yu = nearbyintf(__fadd_rn(64.0f, __fmul_rn(__fmul_rn(a2, 70.0f), 0.5f)));
    float yd = nearbyintf(__fsub_rn(64.0f, __fmul_rn(__fmul_rn(a3, 70.0f), 0.5f)));

    // masks[b] = rotate(box, -azimuth[b]); a = deg2rad(-az)
    const float ang = __fmul_rn(-azimuth[b], 0.017453292519943295f);
    float sn, cs;
    sincosf(ang, &sn, &cs);
    const float nsn = -sn;

    const float4* img4 = reinterpret_cast<const float4*>(img);

    // 4096 float4 per image; unroll x2 with BOTH loads front-batched per
    // iteration so each warp keeps >=2 LDG.128 in flight (MLP).
    #pragma unroll 2
    for (int j = 0; j < 8; j++) {
        const int iA = threadIdx.x + j * 512;
        const int iB = iA + 256;

        const float4 vA = __ldcs(img4 + iA);
        const float4 vB = __ldcs(img4 + iB);

        process4(iA, vA, sn, cs, nsn, xd, xu, yd, yu, targ, cut, scene, raw);
        process4(iB, vB, sn, cs, nsn, xd, xu, yd, yu, targ, cut, scene, raw);
    }
}

extern "C" void kernel_launch(void* const* d_in, const int* in_sizes, int n_in,
                              void* d_out, int out_size)
{
    const float* image   = (const float*)d_in[0];
    const float* azimuth = (const float*)d_in[1];
    const float* alpha   = (const float*)d_in[2];
    float* out = (float*)d_out;

    kd_fused_kernel<<<NB, 256>>>(image, azimuth, alpha, out);
}